// round 17
// baseline (speedup 1.0000x reference)
#include <cuda_runtime.h>
#include <cuda_bf16.h>
#include <cstdint>
typedef uint32_t u32;

constexpr int Bb=2, Hh=12, Ss=4096, Dd=64, BS=64, NB=64, Rr=3, BH=24;
#define NEGV (-10000.0f)
#define LOG2E 1.44269504088896f

constexpr int RSB = 144;               // bf16 smem tile row stride in bytes
constexpr int TILE_B = 64 * RSB;       // 9216 B per 64x64 bf16 tile
constexpr int OFF_MS = 8*TILE_B;       // 2 buffers x [KHI,KLO,VHI,VLO]
constexpr int SMEM_BYTES = OFF_MS + 2*64*4;   // 74240 B -> 3 CTAs/SM

constexpr int NHEAVY = 2*BH;           // 48 heavy q-blocks (qb=0,63 per b,h)
constexpr int NPIECE = 8;              // pieces per heavy block (8 tiles each)
constexpr int HGRID  = NHEAVY*NPIECE;  // 384 heavy-piece CTAs

// device scratch
__device__ __nv_bfloat16 g_kp[(size_t)BH*Ss*128];
__device__ __nv_bfloat16 g_vp[(size_t)BH*Ss*128];
__device__ float g_bias[Bb*Ss];
__device__ float g_part[(size_t)HGRID*BS*Dd];   // per-piece unnormalized O
__device__ float g_plsum[HGRID*BS];             // per-piece row sums

__device__ __forceinline__ u32 smem_u32(const void* p){
    u32 a; asm("{ .reg .u64 t; cvta.to.shared.u64 t, %1; cvt.u32.u64 %0, t; }" : "=r"(a) : "l"(p));
    return a;
}
__device__ __forceinline__ void split2(float a, float b, u32& hi, u32& lo){
    __nv_bfloat16 ha=__float2bfloat16_rn(a), hb=__float2bfloat16_rn(b);
    __nv_bfloat16 la=__float2bfloat16_rn(a-__bfloat162float(ha));
    __nv_bfloat16 lb=__float2bfloat16_rn(b-__bfloat162float(hb));
    hi=(u32)__bfloat16_as_ushort(ha)|((u32)__bfloat16_as_ushort(hb)<<16);
    lo=(u32)__bfloat16_as_ushort(la)|((u32)__bfloat16_as_ushort(lb)<<16);
}
__device__ __forceinline__ void ldsm4(u32& r0,u32& r1,u32& r2,u32& r3, u32 addr){
    asm volatile("ldmatrix.sync.aligned.m8n8.x4.shared.b16 {%0,%1,%2,%3}, [%4];"
        : "=r"(r0),"=r"(r1),"=r"(r2),"=r"(r3) : "r"(addr));
}
__device__ __forceinline__ void ldsm4t(u32& r0,u32& r1,u32& r2,u32& r3, u32 addr){
    asm volatile("ldmatrix.sync.aligned.m8n8.x4.trans.shared.b16 {%0,%1,%2,%3}, [%4];"
        : "=r"(r0),"=r"(r1),"=r"(r2),"=r"(r3) : "r"(addr));
}
__device__ __forceinline__ void mma16816(float* c, const u32* a, u32 b0, u32 b1){
    asm volatile("mma.sync.aligned.m16n8k16.row.col.f32.bf16.bf16.f32 "
        "{%0,%1,%2,%3}, {%4,%5,%6,%7}, {%8,%9}, {%0,%1,%2,%3};"
        : "+f"(c[0]), "+f"(c[1]), "+f"(c[2]), "+f"(c[3])
        : "r"(a[0]), "r"(a[1]), "r"(a[2]), "r"(a[3]), "r"(b0), "r"(b1));
}
__device__ __forceinline__ float ex2f(float x){
    float y; asm("ex2.approx.f32 %0, %1;" : "=f"(y) : "f"(x)); return y;
}
__device__ __forceinline__ void cpa16(u32 dst, const void* src){
    asm volatile("cp.async.cg.shared.global [%0], [%1], 16;" :: "r"(dst), "l"(src));
}
#define CP_COMMIT() asm volatile("cp.async.commit_group;" ::: "memory")
#define CP_WAIT1()  asm volatile("cp.async.wait_group 1;" ::: "memory")

// ---- one-time convert: K/V fp32 -> packed bf16 hi/lo; mask -> log2e bias ----
__global__ void __launch_bounds__(256) convert_kernel(
    const float* __restrict__ k, const float* __restrict__ v, const float* __restrict__ mask)
{
    const size_t idx = (size_t)blockIdx.x*256 + threadIdx.x;
    const size_t row = idx >> 6;
    const int col = (int)(idx & 63);
    float kx = k[idx];
    __nv_bfloat16 h = __float2bfloat16_rn(kx);
    g_kp[row*128 + col]      = h;
    g_kp[row*128 + 64 + col] = __float2bfloat16_rn(kx - __bfloat162float(h));
    float vx = v[idx];
    h = __float2bfloat16_rn(vx);
    g_vp[row*128 + col]      = h;
    g_vp[row*128 + 64 + col] = __float2bfloat16_rn(vx - __bfloat162float(h));
    if (idx < (size_t)Bb*Ss) g_bias[idx] = (1.0f - mask[idx]) * (NEGV * LOG2E);
}

// ---- finalize heavy q-blocks: sum 8 pieces, normalize, apply from_mask ----
__global__ void __launch_bounds__(256) finalize_kernel(
    const float* __restrict__ mask, float* __restrict__ out)
{
    const int hb = blockIdx.x;                  // 0..47
    const int tid = threadIdx.x;
    const int qb = (hb < BH) ? 0 : NB-1;
    const int idx = hb % BH;
    const int b = idx / Hh, h = idx % Hh;
    const size_t bh = (size_t)(b*Hh + h);
    __shared__ float ls[BS];
    if (tid < BS) {
        float s = 0.0f;
        #pragma unroll
        for (int p = 0; p < NPIECE; p++) s += g_plsum[(hb*NPIECE + p)*BS + tid];
        ls[tid] = mask[(size_t)b*Ss + qb*BS + tid] / s;
    }
    __syncthreads();
    const size_t obase = (bh*Ss + (size_t)qb*BS)*Dd;
    for (int e = tid; e < BS*Dd; e += 256) {
        float s = 0.0f;
        #pragma unroll
        for (int p = 0; p < NPIECE; p++) s += g_part[(size_t)(hb*NPIECE + p)*BS*Dd + e];
        out[obase + e] = s * ls[e >> 6];
    }
}

// ---- issue one tile's cp.async group: K hi/lo, V hi/lo, mask bias ----
__device__ __forceinline__ void issue_tile(u32 bufb, u32 msaddr, size_t bh, int b, int kb, int tid)
{
    const char* kp = (const char*)(g_kp + (bh*Ss + (size_t)kb*BS)*128);
    const char* vp = (const char*)(g_vp + (bh*Ss + (size_t)kb*BS)*128);
    #pragma unroll
    for (int i = 0; i < 8; i++) {
        int e = tid + 128*i;
        int row = e >> 4, c = e & 15;
        u32 doff = (u32)((c < 8 ? 0 : TILE_B) + row*RSB + (c & 7)*16);
        cpa16(bufb + doff,            kp + row*256 + c*16);
        cpa16(bufb + 2*TILE_B + doff, vp + row*256 + c*16);
    }
    if (tid < 16) cpa16(msaddr + tid*16, g_bias + (size_t)b*Ss + kb*BS + tid*4);
}

__global__ void __launch_bounds__(128, 3) bigbird_mma_kernel(
    const float* __restrict__ q, const float* __restrict__ mask,
    const int* __restrict__ rand_attn, float* __restrict__ out)
{
    extern __shared__ char smem[];
    const u32 sb = smem_u32(smem);
    float* msf = (float*)(smem + OFF_MS);

    const int tid  = threadIdx.x;
    const int wid  = tid >> 5;
    const int lane = tid & 31;
    const int g    = lane >> 2;
    const int tg   = lane & 3;

    // ---- CTA decode: heavy pieces first, then sparse q-blocks ----
    const int bid = blockIdx.x;
    int qb, idx, pbase = 0;
    bool heavy = (bid < HGRID);
    if (heavy) {
        const int hb = bid >> 3, piece = bid & 7;
        qb = (hb < BH) ? 0 : NB-1;
        idx = hb % BH;
        pbase = piece * 8;
    } else {
        const int m = bid - HGRID;
        qb = 1 + m / BH;                  // 1..62
        idx = m % BH;
    }
    const int b = idx / Hh, h = idx % Hh;
    const size_t bh = (size_t)(b*Hh + h);
    const float* mbase = mask + (size_t)b*Ss;

    // ---- key-block list ----
    int kblocks[8]; int ntile;
    if (heavy) {
        ntile = 8;
        #pragma unroll
        for (int i = 0; i < 8; i++) kblocks[i] = pbase + i;
    } else {
        const int* rp = rand_attn + (bh*(NB-2) + (qb-1))*Rr;
        const int r0 = rp[0], r1 = rp[1], r2 = rp[2];
        if (qb == 1) {
            kblocks[0]=0; kblocks[1]=1; kblocks[2]=2; kblocks[3]=NB-1;
            kblocks[4]=r0; kblocks[5]=r1; kblocks[6]=r2; ntile=7;
        } else if (qb == NB-2) {
            kblocks[0]=0; kblocks[1]=NB-3; kblocks[2]=NB-2; kblocks[3]=NB-1;
            kblocks[4]=r0; kblocks[5]=r1; kblocks[6]=r2; ntile=7;
        } else {
            kblocks[0]=0; kblocks[1]=qb-1; kblocks[2]=qb; kblocks[3]=qb+1;
            kblocks[4]=r0; kblocks[5]=r1; kblocks[6]=r2; kblocks[7]=NB-1; ntile=8;
        }
    }

    // ---- Q: load fp32, fold scale*log2e, split hi/lo into buffer-0 staging ----
    const float SCL = 0.125f * LOG2E;
    const float* qptr = q + (bh*Ss + (size_t)qb*BS)*Dd;
    #pragma unroll
    for (int i = 0; i < 16; i++) {
        int e = tid + 128*i;
        int row = e >> 5, dp = e & 31;
        float2 qv = *(const float2*)(qptr + row*Dd + 2*dp);
        u32 hi, lo; split2(qv.x * SCL, qv.y * SCL, hi, lo);
        *(u32*)(smem + 0      + row*RSB + dp*4) = hi;
        *(u32*)(smem + TILE_B + row*RSB + dp*4) = lo;
    }
    __syncthreads();

    u32 qhi[4][4], qlo[4][4];
    {
        const u32 rowoff = (u32)((16*wid + ((lane>>3)&1)*8 + (lane&7)) * RSB);
        #pragma unroll
        for (int kk = 0; kk < 4; kk++) {
            const u32 coloff = (u32)((16*kk + 8*(lane>>4)) * 2);
            ldsm4(qhi[kk][0], qhi[kk][1], qhi[kk][2], qhi[kk][3], sb + 0      + rowoff + coloff);
            ldsm4(qlo[kk][0], qlo[kk][1], qlo[kk][2], qlo[kk][3], sb + TILE_B + rowoff + coloff);
        }
    }
    __syncthreads();   // Q staging done before cp.async overwrites buf0

    // ---- prologue: pipeline tiles 0 and 1 ----
    issue_tile(sb + 0,        sb + (u32)OFF_MS,       bh, b, kblocks[0], tid);
    CP_COMMIT();
    issue_tile(sb + 4*TILE_B, sb + (u32)OFF_MS + 256, bh, b, kblocks[1], tid);
    CP_COMMIT();

    float oacc[8][4];
    #pragma unroll
    for (int j = 0; j < 8; j++) { oacc[j][0]=0; oacc[j][1]=0; oacc[j][2]=0; oacc[j][3]=0; }
    float lsum0 = 0.0f, lsum1 = 0.0f;

    for (int t = 0; t < ntile; t++) {
        const int buf = t & 1;
        const u32 bufb = sb + (u32)(buf*4*TILE_B);

        CP_WAIT1();
        __syncthreads();

        // ---- S = Q K^T (3 split passes) ----
        float sacc[8][4];
        #pragma unroll
        for (int j = 0; j < 8; j++) { sacc[j][0]=0; sacc[j][1]=0; sacc[j][2]=0; sacc[j][3]=0; }

        #pragma unroll
        for (int j = 0; j < 8; j++) {
            const u32 krowoff = (u32)((8*j + (lane&7)) * RSB + (8*(lane>>3)) * 2);
            u32 kh[8], kl[8];
            ldsm4(kh[0], kh[1], kh[2], kh[3], bufb + 0*TILE_B + krowoff);
            ldsm4(kh[4], kh[5], kh[6], kh[7], bufb + 0*TILE_B + krowoff + 64);
            ldsm4(kl[0], kl[1], kl[2], kl[3], bufb + 1*TILE_B + krowoff);
            ldsm4(kl[4], kl[5], kl[6], kl[7], bufb + 1*TILE_B + krowoff + 64);
            #pragma unroll
            for (int kk = 0; kk < 4; kk++) {
                mma16816(sacc[j], qhi[kk], kh[2*kk], kh[2*kk+1]);
                mma16816(sacc[j], qlo[kk], kh[2*kk], kh[2*kk+1]);
                mma16816(sacc[j], qhi[kk], kl[2*kk], kl[2*kk+1]);
            }
        }

        // ---- softmax: p = 2^(s' + bias') ----
        #pragma unroll
        for (int j = 0; j < 8; j++) {
            const float km0 = msf[buf*64 + 8*j + 2*tg];
            const float km1 = msf[buf*64 + 8*j + 2*tg + 1];
            sacc[j][0] = ex2f(sacc[j][0] + km0);
            sacc[j][1] = ex2f(sacc[j][1] + km1);
            sacc[j][2] = ex2f(sacc[j][2] + km0);
            sacc[j][3] = ex2f(sacc[j][3] + km1);
            lsum0 += sacc[j][0] + sacc[j][1];
            lsum1 += sacc[j][2] + sacc[j][3];
        }

        // ---- O += P V (3 split passes) ----
        #pragma unroll
        for (int kk = 0; kk < 4; kk++) {
            const int j0 = 2*kk, j1 = 2*kk + 1;
            u32 ahi[4], alo[4];
            split2(sacc[j0][0], sacc[j0][1], ahi[0], alo[0]);
            split2(sacc[j0][2], sacc[j0][3], ahi[1], alo[1]);
            split2(sacc[j1][0], sacc[j1][1], ahi[2], alo[2]);
            split2(sacc[j1][2], sacc[j1][3], ahi[3], alo[3]);

            const u32 vrowoff = (u32)((16*kk + 8*((lane>>3)&1) + (lane&7)) * RSB + (8*(lane>>4)) * 2);
            u32 vh[16], vl[16];
            #pragma unroll
            for (int h2 = 0; h2 < 4; h2++) {
                ldsm4t(vh[4*h2], vh[4*h2+1], vh[4*h2+2], vh[4*h2+3], bufb + 2*TILE_B + vrowoff + 32*h2);
                ldsm4t(vl[4*h2], vl[4*h2+1], vl[4*h2+2], vl[4*h2+3], bufb + 3*TILE_B + vrowoff + 32*h2);
            }
            #pragma unroll
            for (int jd = 0; jd < 8; jd++) {
                mma16816(oacc[jd], ahi, vh[2*jd], vh[2*jd+1]);
                mma16816(oacc[jd], alo, vh[2*jd], vh[2*jd+1]);
                mma16816(oacc[jd], ahi, vl[2*jd], vl[2*jd+1]);
            }
        }
        __syncthreads();

        if (t + 2 < ntile) {
            issue_tile(bufb, sb + (u32)(OFF_MS + buf*256), bh, b, kblocks[t+2], tid);
        }
        CP_COMMIT();
    }

    // ---- epilogue ----
    lsum0 += __shfl_xor_sync(0xffffffffu, lsum0, 1);
    lsum0 += __shfl_xor_sync(0xffffffffu, lsum0, 2);
    lsum1 += __shfl_xor_sync(0xffffffffu, lsum1, 1);
    lsum1 += __shfl_xor_sync(0xffffffffu, lsum1, 2);

    const int row0 = 16*wid + g;
    const int row1 = row0 + 8;
    if (heavy) {
        // write unnormalized partials to this piece's private slot
        float* pp = g_part + (size_t)bid*BS*Dd;
        #pragma unroll
        for (int jd = 0; jd < 8; jd++) {
            const int c0 = 8*jd + 2*tg;
            *(float2*)(pp + row0*Dd + c0) = make_float2(oacc[jd][0], oacc[jd][1]);
            *(float2*)(pp + row1*Dd + c0) = make_float2(oacc[jd][2], oacc[jd][3]);
        }
        if (tg == 0) {
            g_plsum[bid*BS + row0] = lsum0;
            g_plsum[bid*BS + row1] = lsum1;
        }
    } else {
        const float inv0 = mbase[qb*BS + row0] / lsum0;
        const float inv1 = mbase[qb*BS + row1] / lsum1;
        float* op = out + (bh*Ss + (size_t)qb*BS)*Dd;
        #pragma unroll
        for (int jd = 0; jd < 8; jd++) {
            const int c0 = 8*jd + 2*tg;
            *(float2*)(op + row0*Dd + c0) = make_float2(oacc[jd][0]*inv0, oacc[jd][1]*inv0);
            *(float2*)(op + row1*Dd + c0) = make_float2(oacc[jd][2]*inv1, oacc[jd][3]*inv1);
        }
    }
}

extern "C" void kernel_launch(void* const* d_in, const int* in_sizes, int n_in,
                              void* d_out, int out_size)
{
    const float* q    = (const float*)d_in[0];
    const float* k    = (const float*)d_in[1];
    const float* v    = (const float*)d_in[2];
    const float* mask = (const float*)d_in[3];
    const int*   ra   = (const int*)d_in[4];
    float* out = (float*)d_out;

    convert_kernel<<<(BH*Ss*Dd)/256, 256>>>(k, v, mask);

    cudaFuncSetAttribute(bigbird_mma_kernel,
                         cudaFuncAttributeMaxDynamicSharedMemorySize, SMEM_BYTES);
    const int grid = HGRID + (NB-2)*BH;   // 384 heavy pieces + 1488 sparse
    bigbird_mma_kernel<<<grid, 128, SMEM_BYTES>>>(q, mask, ra, out);

    finalize_kernel<<<NHEAVY, 256>>>(mask, out);
}